// round 16
// baseline (speedup 1.0000x reference)
#include <cuda_runtime.h>
#include <cuda_fp16.h>
#include <cstdint>

#define L2D 147456   // 384*384
#define IMG 384
#define NPIX_INV (1.0/147456.0)

// ---------------- static scratch ----------------
__device__ float g_x1n[788*384];
__device__ float g_row[64*384];
__device__ float g_col[64*384];
__device__ float g_Ag[64*384];
__device__ float g_Bg[64*384];
__device__ float g_c2[64];
__device__ double g_x2s[210];
__device__ double g_x2q[210];
__device__ float g_nsc[16*64];
__device__ float g_nsh[16*64];

__device__ __half g_wswh[10*64*576];   // fp16 conv weights, [l2k][co][k = tap*64 + ci]
__device__ __half g_w2h[64*256];       // fp16 pair2 weights (norm-folded), [co][k], zero-padded
__device__ __half g_w3h[64*128];       // fp16 mix weights, [co][k]
__device__ float g_pS[64*1152];
__device__ float g_pQ[64*1152];

// NHWC fp32 buffers [pix][64]
__device__ float g_bufP[L2D*64];
__device__ float g_bufR[L2D*64];
__device__ float g_bufX[L2D*64];
__device__ float g_bufT[L2D*64];
// NHWC fp16 activation copy for conv<false> gathers
__device__ __half g_actH[L2D*64];

// ---------------- helpers ----------------
__device__ __forceinline__ uint32_t smem_u32(const void* p){
    uint32_t a;
    asm("{ .reg .u64 t; cvta.to.shared.u64 t, %1; cvt.u32.u64 %0, t; }" : "=r"(a) : "l"(p));
    return a;
}
__device__ __forceinline__ void mma_f16_16n8k16(float* c, const uint32_t* a, const uint32_t* b){
    asm volatile("mma.sync.aligned.m16n8k16.row.col.f32.f16.f16.f32 "
        "{%0,%1,%2,%3}, {%4,%5,%6,%7}, {%8,%9}, {%0,%1,%2,%3};"
        : "+f"(c[0]), "+f"(c[1]), "+f"(c[2]), "+f"(c[3])
        : "r"(a[0]), "r"(a[1]), "r"(a[2]), "r"(a[3]), "r"(b[0]), "r"(b[1]));
}
__device__ __forceinline__ void ldsm_x4(uint32_t& r0, uint32_t& r1, uint32_t& r2, uint32_t& r3,
                                        uint32_t addr){
    asm volatile("ldmatrix.sync.aligned.m8n8.x4.shared.b16 {%0,%1,%2,%3}, [%4];"
        : "=r"(r0), "=r"(r1), "=r"(r2), "=r"(r3) : "r"(addr));
}

__device__ __forceinline__ void blockReduce2(float& s, float& q, float* sm) {
    __syncthreads();
    int lane = threadIdx.x & 31, w = threadIdx.x >> 5;
    #pragma unroll
    for (int o = 16; o; o >>= 1) {
        s += __shfl_down_sync(0xffffffffu, s, o);
        q += __shfl_down_sync(0xffffffffu, q, o);
    }
    if (lane == 0) { sm[2*w] = s; sm[2*w+1] = q; }
    __syncthreads();
    int nw = blockDim.x >> 5;
    if (threadIdx.x == 0) {
        float S = 0.f, Q = 0.f;
        for (int i = 0; i < nw; i++) { S += sm[2*i]; Q += sm[2*i+1]; }
        sm[0] = S; sm[1] = Q;
    }
    __syncthreads();
    s = sm[0]; q = sm[1];
}

__device__ __forceinline__ float lrelu(float v) { return v < 0.f ? 0.01f*v : v; }

// ---------------- zero stats ----------------
__global__ void k_zero() {
    int t = threadIdx.x;
    if (t < 210) { g_x2s[t] = 0.0; g_x2q[t] = 0.0; }
}

// ---------------- weight prep ----------------
__global__ void k_wprep(const float* __restrict__ rw) {
    int i = blockIdx.x*256 + threadIdx.x;
    if (i >= 10*64*64*9) return;
    int tap = i % 9; int r = i / 9;
    int ci = r & 63; r >>= 6;
    int co = r & 63; int l2k = r >> 6;
    g_wswh[(l2k*64 + co)*576 + tap*64 + ci] = __float2half(rw[i]);
}
__global__ void k_w3prep(const float* __restrict__ W3) {
    int i = blockIdx.x*256 + threadIdx.x;   // 8192
    g_w3h[i] = __float2half(W3[i]);
}

// ---------------- x_1d instance norm ----------------
__global__ void k1_norm1d(const float* __restrict__ x) {
    __shared__ float sm[32];
    int d = blockIdx.x;
    float v = x[d*384 + threadIdx.x];
    float s = v, q = v*v;
    blockReduce2(s, q, sm);
    float mu = s * (1.f/384.f);
    float var = q * (1.f/384.f) - mu*mu;
    float iv = rsqrtf(var + 1e-5f);
    g_x1n[d*384 + threadIdx.x] = (v - mu) * iv;
}

// ---------------- x_2d per-channel stats (float4) ----------------
__global__ void k2_x2stats(const float* __restrict__ x2) {
    __shared__ float sm[32];
    int c = blockIdx.y;
    const float4* p = (const float4*)(x2 + c*L2D + blockIdx.x*4096);
    float s = 0.f, q = 0.f;
    #pragma unroll
    for (int k = 0; k < 4; k++) {
        float4 v = p[threadIdx.x + k*256];
        s += v.x + v.y + v.z + v.w;
        q += v.x*v.x + v.y*v.y + v.z*v.z + v.w*v.w;
    }
    blockReduce2(s, q, sm);
    if (threadIdx.x == 0) {
        atomicAdd(&g_x2s[c], (double)s);
        atomicAdd(&g_x2q[c], (double)q);
    }
}

// ---------------- fold x2 norm into W2 -> fp16 (zero-padded K=256) ----------------
__global__ void k2b_scaleW2(const float* __restrict__ W2) {
    __shared__ float smu[210], siv[210];
    __shared__ float sm[32];
    int t = threadIdx.x, co = blockIdx.x;
    if (t < 210) {
        float mu = (float)(g_x2s[t] * NPIX_INV);
        float var = (float)(g_x2q[t] * NPIX_INV) - mu*mu;
        smu[t] = mu; siv[t] = rsqrtf(var + 1e-5f);
    }
    __syncthreads();
    float a = 0.f;
    float w = 0.f;
    if (t < 210) {
        w = W2[co*210 + t];
        a = w * smu[t] * siv[t];
    }
    g_w2h[co*256 + t] = __float2half(t < 210 ? w * siv[t] : 0.f);
    float dummy = 0.f;
    blockReduce2(a, dummy, sm);
    if (t == 0) g_c2[co] = -a;
}

// ---------------- row/col projections ----------------
__global__ void k3_rowcol(const float* __restrict__ W1) {
    int c = blockIdx.x >> 1, which = blockIdx.x & 1;
    const float* w = W1 + c*1576 + which*788;
    int l = threadIdx.x;
    float acc = 0.f;
    #pragma unroll 4
    for (int d = 0; d < 788; d++) acc += w[d] * g_x1n[d*384 + l];
    (which ? g_col : g_row)[c*384 + l] = acc;
}

// ---------------- pair1 separable stats ----------------
__global__ void k3b_pair1(const float* __restrict__ g1, const float* __restrict__ b1) {
    __shared__ float sm[32];
    int c = blockIdx.x, t = threadIdx.x;
    float sr = 0.f, qr = 0.f, sc_ = 0.f, qc = 0.f;
    for (int i = t; i < 384; i += 128) {
        float r = g_row[c*384+i]; sr += r; qr += r*r;
        float cl = g_col[c*384+i]; sc_ += cl; qc += cl*cl;
    }
    blockReduce2(sr, qr, sm);
    blockReduce2(sc_, qc, sm);
    float mur = sr*(1.f/384.f), muc = sc_*(1.f/384.f);
    float var = (qr*(1.f/384.f) - mur*mur) + (qc*(1.f/384.f) - muc*muc);
    float iv = rsqrtf(var + 1e-5f);
    float mu = mur + muc;
    float gc = g1[c], bc = b1[c];
    for (int i = t; i < 384; i += 128) {
        g_Ag[c*384+i] = gc*iv*(g_row[c*384+i] - mu) + bc;
        g_Bg[c*384+i] = gc*iv*g_col[c*384+i];
    }
}

// ---------------- finalize stats from per-CTA partials ----------------
__global__ void k_finred(int idx, const float* __restrict__ g, const float* __restrict__ b) {
    __shared__ float sm[32];
    int ch = blockIdx.x;
    float s = 0.f, q = 0.f;
    for (int i = threadIdx.x; i < 1152; i += 256) {
        s += g_pS[ch*1152 + i];
        q += g_pQ[ch*1152 + i];
    }
    blockReduce2(s, q, sm);
    if (threadIdx.x == 0) {
        float mu = s * (float)NPIX_INV;
        float var = q * (float)NPIX_INV - mu*mu;
        float iv = rsqrtf(var + 1e-5f);
        g_nsc[idx*64+ch] = g[ch]*iv;
        g_nsh[idx*64+ch] = b[ch] - g[ch]*iv*mu;
    }
}

// ---------------- NHWC apply: carrier fp32 + fp16 copy ----------------
__global__ void k_apply_nhwc(const float4* __restrict__ raw, int idx,
                             const float4* __restrict__ res, float4* __restrict__ carrier) {
    int i4 = blockIdx.x*256 + threadIdx.x;      // over L2D*16
    int c = (i4 & 15) * 4;
    float4 sc = *(const float4*)&g_nsc[idx*64+c];
    float4 sh = *(const float4*)&g_nsh[idx*64+c];
    float4 v = raw[i4];
    v.x = lrelu(v.x*sc.x + sh.x);
    v.y = lrelu(v.y*sc.y + sh.y);
    v.z = lrelu(v.z*sc.z + sh.z);
    v.w = lrelu(v.w*sc.w + sh.w);
    if (res) {
        float4 r = res[i4];
        v.x += r.x; v.y += r.y; v.z += r.z; v.w += r.w;
    }
    carrier[i4] = v;
    __half2 h0 = __floats2half2_rn(v.x, v.y);
    __half2 h1 = __floats2half2_rn(v.z, v.w);
    uint2 u; u.x = *(uint32_t*)&h0; u.y = *(uint32_t*)&h1;
    *(uint2*)&g_actH[(size_t)i4*4] = u;
}

// ---------------- final apply: NHWC raw + NHWC res -> NCHW fp32 out ----------------
__global__ void k_apply_tr(const float* __restrict__ raw, int idx,
                           const float* __restrict__ res, float* __restrict__ out) {
    __shared__ float tile[64*65];
    __shared__ float s_sc[64], s_sh[64];
    int tid = threadIdx.x;
    int pix0 = blockIdx.x * 64;
    if (tid < 64) { s_sc[tid] = g_nsc[idx*64+tid]; s_sh[tid] = g_nsh[idx*64+tid]; }
    __syncthreads();
    #pragma unroll
    for (int j = 0; j < 4; j++) {
        int e = tid + j*256;                  // 1024 float4 units
        int c4 = e & 15, px = e >> 4;
        float4 v = *(const float4*)(raw + ((size_t)(pix0+px))*64 + c4*4);
        float4 r = *(const float4*)(res + ((size_t)(pix0+px))*64 + c4*4);
        int c = c4*4;
        tile[(c+0)*65+px] = lrelu(v.x*s_sc[c+0] + s_sh[c+0]) + r.x;
        tile[(c+1)*65+px] = lrelu(v.y*s_sc[c+1] + s_sh[c+1]) + r.y;
        tile[(c+2)*65+px] = lrelu(v.z*s_sc[c+2] + s_sh[c+2]) + r.z;
        tile[(c+3)*65+px] = lrelu(v.w*s_sc[c+3] + s_sh[c+3]) + r.w;
    }
    __syncthreads();
    #pragma unroll
    for (int j = 0; j < 16; j++) {
        int e = tid + j*256;                  // 4096 floats
        int px = e & 63, c = e >> 6;
        out[(size_t)c*L2D + pix0 + px] = tile[c*65 + px];
    }
}

// ---- shared epilogue: bias + NHWC raw store + per-channel partial stats ----
struct EpiSmem { float rs[8][4][8]; float rq[8][4][8]; };

__device__ __forceinline__ void conv_epilogue(
    float acc[2][4][4], const float* s_bias, EpiSmem* es,
    int wm, int wn, int wid, int lane, int rA, int qA,
    int y, int x0, int cta, float* __restrict__ out)
{
    float ss[4][2], qq[4][2];
    #pragma unroll
    for (int nt = 0; nt < 4; nt++) { ss[nt][0]=0.f; ss[nt][1]=0.f; qq[nt][0]=0.f; qq[nt][1]=0.f; }
    int pbase = y*IMG + x0 + wm*32;
    #pragma unroll
    for (int nt = 0; nt < 4; nt++) {
        int coA = wn*32 + nt*8 + 2*qA;
        float bA = s_bias ? s_bias[coA] : 0.f;
        float bB = s_bias ? s_bias[coA+1] : 0.f;
        #pragma unroll
        for (int mt = 0; mt < 2; mt++) {
            int px = pbase + mt*16 + rA;
            float v0 = acc[mt][nt][0] + bA;
            float v1 = acc[mt][nt][1] + bB;
            float v2 = acc[mt][nt][2] + bA;
            float v3 = acc[mt][nt][3] + bB;
            float2 w0 = make_float2(v0, v1);
            float2 w1 = make_float2(v2, v3);
            *(float2*)&out[(size_t)px*64 + coA]       = w0;
            *(float2*)&out[(size_t)(px+8)*64 + coA]   = w1;
            ss[nt][0] += v0 + v2;  qq[nt][0] += v0*v0 + v2*v2;
            ss[nt][1] += v1 + v3;  qq[nt][1] += v1*v1 + v3*v3;
        }
    }
    #pragma unroll
    for (int nt = 0; nt < 4; nt++)
        #pragma unroll
        for (int e = 0; e < 2; e++) {
            float s = ss[nt][e], q = qq[nt][e];
            s += __shfl_down_sync(0xffffffffu, s, 16);
            q += __shfl_down_sync(0xffffffffu, q, 16);
            s += __shfl_down_sync(0xffffffffu, s, 8);
            q += __shfl_down_sync(0xffffffffu, q, 8);
            s += __shfl_down_sync(0xffffffffu, s, 4);
            q += __shfl_down_sync(0xffffffffu, q, 4);
            ss[nt][e] = s; qq[nt][e] = q;
        }
    if (lane < 4) {
        #pragma unroll
        for (int nt = 0; nt < 4; nt++) {
            es->rs[wid][lane][nt*2]   = ss[nt][0];  es->rq[wid][lane][nt*2]   = qq[nt][0];
            es->rs[wid][lane][nt*2+1] = ss[nt][1];  es->rq[wid][lane][nt*2+1] = qq[nt][1];
        }
    }
    __syncthreads();
    int tid = threadIdx.x;
    if (tid < 64) {
        int wn2 = tid >> 5, rem = tid & 31;
        int nt = rem >> 3, low = rem & 7, qa2 = low >> 1, e = low & 1;
        float s = 0.f, q = 0.f;
        #pragma unroll
        for (int wm2 = 0; wm2 < 4; wm2++) {
            s += es->rs[wn2*4 + wm2][qa2][nt*2 + e];
            q += es->rq[wn2*4 + wm2][qa2][nt*2 + e];
        }
        g_pS[tid*1152 + cta] = s;
        g_pQ[tid*1152 + cta] = q;
    }
}

// ================= fp16 m16n8k16 implicit-GEMM conv (ldmatrix, NHWC) =================
#define A_STRIDE_H 72
#define W_STRIDE_H 72
#define CONV_SMEM ((2*128*A_STRIDE_H + 2*64*W_STRIDE_H)*2)

// APPLY=false: input = g_actH (fp16 NHWC, pre-normalized). APPLY=true: input = inF (fp32 NHWC raw, fused norm).
template<bool APPLY>
__global__ void __launch_bounds__(256, 2)
conv_mma(const float* __restrict__ inF, int aidx, const __half* __restrict__ wsrc,
         int D, const float* __restrict__ bias, float* __restrict__ out)
{
    extern __shared__ __half smh[];
    __half* sA = smh;
    __half* sW = smh + 2*128*A_STRIDE_H;
    __shared__ float s_bias[64];
    __shared__ float s_nsc[64], s_nsh[64];
    __shared__ EpiSmem es;

    int tid = threadIdx.x, lane = tid & 31, wid = tid >> 5;
    int x0 = blockIdx.x * 128, y = blockIdx.y;
    int cta = blockIdx.y * 3 + blockIdx.x;
    int wm = wid & 3, wn = wid >> 2;
    int rA = lane >> 2, qA = lane & 3;

    if (tid < 64) {
        s_bias[tid] = bias[tid];
        if (APPLY) { s_nsc[tid] = g_nsc[aidx*64 + tid]; s_nsh[tid] = g_nsh[aidx*64 + tid]; }
    }
    if (APPLY) __syncthreads();

    float acc[2][4][4];
    #pragma unroll
    for (int mt = 0; mt < 2; mt++)
        #pragma unroll
        for (int nt = 0; nt < 4; nt++)
            #pragma unroll
            for (int r = 0; r < 4; r++) acc[mt][nt][r] = 0.f;

    uint4 stg[4];
    uint4 wstg[2];

    auto ldchunk = [&](int tap) {
        int dy = (tap/3 - 1)*D, dx = (tap%3 - 1)*D;
        int gy = y + dy;
        bool gyok = ((unsigned)gy < 384u);
        #pragma unroll
        for (int r = 0; r < 4; r++) {
            int e = tid + r*256;
            int kg = e & 7, px = e >> 3;
            int gx = x0 + px + dx;
            uint4 v = make_uint4(0u, 0u, 0u, 0u);
            if (gyok && (unsigned)gx < 384u) {
                long base = (long)(gy*IMG + gx)*64 + kg*8;
                if (APPLY) {
                    const float* p = inF + base;
                    float4 va = *(const float4*)p;
                    float4 vb = *(const float4*)(p + 4);
                    int cb = kg*8;
                    float f0 = lrelu(va.x*s_nsc[cb]   + s_nsh[cb]);
                    float f1 = lrelu(va.y*s_nsc[cb+1] + s_nsh[cb+1]);
                    float f2 = lrelu(va.z*s_nsc[cb+2] + s_nsh[cb+2]);
                    float f3 = lrelu(va.w*s_nsc[cb+3] + s_nsh[cb+3]);
                    float f4 = lrelu(vb.x*s_nsc[cb+4] + s_nsh[cb+4]);
                    float f5 = lrelu(vb.y*s_nsc[cb+5] + s_nsh[cb+5]);
                    float f6 = lrelu(vb.z*s_nsc[cb+6] + s_nsh[cb+6]);
                    float f7 = lrelu(vb.w*s_nsc[cb+7] + s_nsh[cb+7]);
                    __half2 h0 = __floats2half2_rn(f0, f1);
                    __half2 h1 = __floats2half2_rn(f2, f3);
                    __half2 h2 = __floats2half2_rn(f4, f5);
                    __half2 h3 = __floats2half2_rn(f6, f7);
                    v.x = *(uint32_t*)&h0; v.y = *(uint32_t*)&h1;
                    v.z = *(uint32_t*)&h2; v.w = *(uint32_t*)&h3;
                } else {
                    v = *(const uint4*)(g_actH + base);
                }
            }
            stg[r] = v;
        }
    };
    auto stchunk = [&](int b) {
        char* abuf = (char*)(sA + b*128*A_STRIDE_H);
        #pragma unroll
        for (int r = 0; r < 4; r++) {
            int e = tid + r*256;
            int kg = e & 7, px = e >> 3;
            *(uint4*)(abuf + px*144 + kg*16) = stg[r];
        }
    };
    auto ldw = [&](int tap) {
        const uint4* ps = (const uint4*)(wsrc + (tid>>2)*576 + tap*64 + (tid&3)*16);
        wstg[0] = ps[0];
        wstg[1] = ps[1];
    };
    auto stw = [&](int b) {
        char* wb = (char*)(sW + b*64*W_STRIDE_H) + (tid>>2)*144 + (tid&3)*32;
        *(uint4*)wb = wstg[0];
        *((uint4*)wb + 1) = wstg[1];
    };

    ldchunk(0); ldw(0);
    stchunk(0); stw(0);
    __syncthreads();

    uint32_t aBase = smem_u32(sA) + (uint32_t)(((wm*32 + (lane & 15))*A_STRIDE_H
                    + ((lane >> 4) << 3)) * 2);
    uint32_t bBase = smem_u32(sW) + (uint32_t)(((wn*32 + (lane & 7) + ((lane >> 4) << 3))*W_STRIDE_H
                    + (lane & 8)) * 2);

    #pragma unroll 1
    for (int c = 0; c < 9; c++) {
        int b = c & 1;
        if (c + 1 < 9) { ldchunk(c + 1); ldw(c + 1); }

        uint32_t aOff = aBase + (uint32_t)(b*128*A_STRIDE_H*2);
        uint32_t bOff = bBase + (uint32_t)(b*64*W_STRIDE_H*2);
        #pragma unroll
        for (int ks = 0; ks < 4; ks++) {
            uint32_t a[2][4], bf[4][2];
            ldsm_x4(a[0][0], a[0][1], a[0][2], a[0][3], aOff + ks*32);
            ldsm_x4(a[1][0], a[1][1], a[1][2], a[1][3], aOff + 16*A_STRIDE_H*2 + ks*32);
            ldsm_x4(bf[0][0], bf[0][1], bf[1][0], bf[1][1], bOff + ks*32);
            ldsm_x4(bf[2][0], bf[2][1], bf[3][0], bf[3][1], bOff + 16*W_STRIDE_H*2 + ks*32);
            #pragma unroll
            for (int mt = 0; mt < 2; mt++)
                #pragma unroll
                for (int nt = 0; nt < 4; nt++)
                    mma_f16_16n8k16(acc[mt][nt], a[mt], bf[nt]);
        }
        if (c + 1 < 9) { stchunk(b ^ 1); stw(b ^ 1); }
        __syncthreads();
    }

    conv_epilogue(acc, s_bias, &es, wm, wn, wid, lane, rA, qA, y, x0, cta, out);
}

// ================= pair2 as mma: bufP = W2h @ x2h + c2 (NCHW x2 in, NHWC out) =================
__global__ void __launch_bounds__(256, 2)
k4_mma(const float* __restrict__ x2, float* __restrict__ out)
{
    extern __shared__ __half smh4[];
    __half* sA = smh4;
    __half* sW = smh4 + 2*128*A_STRIDE_H;
    __shared__ float s_bias[64];
    __shared__ EpiSmem es;

    int tid = threadIdx.x, lane = tid & 31, wid = tid >> 5;
    int x0 = blockIdx.x * 128, y = blockIdx.y;
    int cta = blockIdx.y * 3 + blockIdx.x;
    int wm = wid & 3, wn = wid >> 2;
    int rA = lane >> 2, qA = lane & 3;

    if (tid < 64) s_bias[tid] = g_c2[tid];

    float acc[2][4][4];
    #pragma unroll
    for (int mt = 0; mt < 2; mt++)
        #pragma unroll
        for (int nt = 0; nt < 4; nt++)
            #pragma unroll
            for (int r = 0; r < 4; r++) acc[mt][nt][r] = 0.f;

    uint4 stg[4];
    uint4 wstg[2];
    int pix0 = y*IMG + x0;

    auto ldchunk = [&](int c) {
        #pragma unroll
        for (int r = 0; r < 4; r++) {
            int e = tid + r*256;
            int px = e & 127, kg = e >> 7;
            int d0 = c*64 + kg*8;
            const float* p = x2 + d0*L2D + pix0 + px;
            float f[8];
            #pragma unroll
            for (int u = 0; u < 8; u++)
                f[u] = (d0 + u < 210) ? p[u*L2D] : 0.f;
            __half2 h0 = __floats2half2_rn(f[0], f[1]);
            __half2 h1 = __floats2half2_rn(f[2], f[3]);
            __half2 h2 = __floats2half2_rn(f[4], f[5]);
            __half2 h3 = __floats2half2_rn(f[6], f[7]);
            uint4 v; v.x = *(uint32_t*)&h0; v.y = *(uint32_t*)&h1;
            v.z = *(uint32_t*)&h2; v.w = *(uint32_t*)&h3;
            stg[r] = v;
        }
    };
    auto stchunk = [&](int b) {
        char* abuf = (char*)(sA + b*128*A_STRIDE_H);
        #pragma unroll
        for (int r = 0; r < 4; r++) {
            int e = tid + r*256;
            int px = e & 127, kg = e >> 7;
            *(uint4*)(abuf + px*144 + kg*16) = stg[r];
        }
    };
    auto ldw = [&](int c) {
        const uint4* ps = (const uint4*)(g_w2h + (tid>>2)*256 + c*64 + (tid&3)*16);
        wstg[0] = ps[0];
        wstg[1] = ps[1];
    };
    auto stw = [&](int b) {
        char* wb = (char*)(sW + b*64*W_STRIDE_H) + (tid>>2)*144 + (tid&3)*32;
        *(uint4*)wb = wstg[0];
        *((uint4*)wb + 1) = wstg[1];
    };

    ldchunk(0); ldw(0);
    stchunk(0); stw(0);
    __syncthreads();

    uint32_t aBase = smem_u32(sA) + (uint32_t)(((wm*32 + (lane & 15))*A_STRIDE_H
                    + ((lane >> 4) << 3)) * 2);
    uint32_t bBase = smem_u32(sW) + (uint32_t)(((wn*32 + (lane & 7) + ((lane >> 4) << 3))*W_STRIDE_H
                    + (lane & 8)) * 2);

    #pragma unroll 1
    for (int c = 0; c < 4; c++) {
        int b = c & 1;
        if (c + 1 < 4) { ldchunk(c + 1); ldw(c + 1); }

        uint32_t aOff = aBase + (uint32_t)(b*128*A_STRIDE_H*2);
        uint32_t bOff = bBase + (uint32_t)(b*64*W_STRIDE_H*2);
        #pragma unroll
        for (int ks = 0; ks < 4; ks++) {
            uint32_t a[2][4], bf[4][2];
            ldsm_x4(a[0][0], a[0][1], a[0][2], a[0][3], aOff + ks*32);
            ldsm_x4(a[1][0], a[1][1], a[1][2], a[1][3], aOff + 16*A_STRIDE_H*2 + ks*32);
            ldsm_x4(bf[0][0], bf[0][1], bf[1][0], bf[1][1], bOff + ks*32);
            ldsm_x4(bf[2][0], bf[2][1], bf[3][0], bf[3][1], bOff + 16*W_STRIDE_H*2 + ks*32);
            #pragma unroll
            for (int mt = 0; mt < 2; mt++)
                #pragma unroll
                for (int nt = 0; nt < 4; nt++)
                    mma_f16_16n8k16(acc[mt][nt], a[mt], bf[nt]);
        }
        if (c + 1 < 4) { stchunk(b ^ 1); stw(b ^ 1); }
        __syncthreads();
    }

    conv_epilogue(acc, s_bias, &es, wm, wn, wid, lane, rA, qA, y, x0, cta, out);
}

// ================= mix as mma: pair = W3 @ [p1n; p2n] (NHWC out) =================
#define A5_STRIDE_H 136
#define W5_STRIDE_H 136
#define MIX_SMEM ((128*A5_STRIDE_H + 64*W5_STRIDE_H)*2)

__global__ void __launch_bounds__(256, 2)
k5_mma(float* __restrict__ out)
{
    extern __shared__ __half smh5[];
    __half* sA = smh5;
    __half* sW = smh5 + 128*A5_STRIDE_H;
    __shared__ float s_nsc[64], s_nsh[64];
    __shared__ EpiSmem es;

    int tid = threadIdx.x, lane = tid & 31, wid = tid >> 5;
    int x0 = blockIdx.x * 128, y = blockIdx.y;
    int cta = blockIdx.y * 3 + blockIdx.x;
    int wm = wid & 3, wn = wid >> 2;
    int rA = lane >> 2, qA = lane & 3;

    if (tid < 64) { s_nsc[tid] = g_nsc[tid]; s_nsh[tid] = g_nsh[tid]; }
    __syncthreads();

    {
        const uint4* ps = (const uint4*)g_w3h;
        char* wb = (char*)sW;
        #pragma unroll
        for (int r = 0; r < 4; r++) {
            int u = tid + r*256;
            int co = u >> 4, seg = u & 15;
            *(uint4*)(wb + co*272 + seg*16) = ps[u];
        }
    }
    {
        char* ab = (char*)sA;
        #pragma unroll
        for (int r = 0; r < 4; r++) {
            int e = tid + r*256;
            int kg = e & 7, px = e >> 3;
            int gx = x0 + px, cb = kg*8;
            float f[8];
            #pragma unroll
            for (int u = 0; u < 8; u++)
                f[u] = lrelu(g_Ag[(cb+u)*384 + y] + g_Bg[(cb+u)*384 + gx]);
            __half2 h0 = __floats2half2_rn(f[0], f[1]);
            __half2 h1 = __floats2half2_rn(f[2], f[3]);
            __half2 h2 = __floats2half2_rn(f[4], f[5]);
            __half2 h3 = __floats2half2_rn(f[6], f[7]);
            uint4 v; v.x = *(uint32_t*)&h0; v.y = *(uint32_t*)&h1;
            v.z = *(uint32_t*)&h2; v.w = *(uint32_t*)&h3;
            *(uint4*)(ab + px*272 + kg*16) = v;
        }
        int pix0 = y*IMG + x0;
        #pragma unroll
        for (int r = 0; r < 4; r++) {
            int e = tid + r*256;
            int kg = e & 7, px = e >> 3;
            int cb = kg*8;
            const float* p = g_bufP + ((size_t)(pix0+px))*64 + cb;
            float4 va = *(const float4*)p;
            float4 vb = *(const float4*)(p + 4);
            float f0 = lrelu(va.x*s_nsc[cb]   + s_nsh[cb]);
            float f1 = lrelu(va.y*s_nsc[cb+1] + s_nsh[cb+1]);
            float f2 = lrelu(va.z*s_nsc[cb+2] + s_nsh[cb+2]);
            float f3 = lrelu(va.w*s_nsc[cb+3] + s_nsh[cb+3]);
            float f4 = lrelu(vb.x*s_nsc[cb+4] + s_nsh[cb+4]);
            float f5 = lrelu(vb.y*s_nsc[cb+5] + s_nsh[cb+5]);
            float f6 = lrelu(vb.z*s_nsc[cb+6] + s_nsh[cb+6]);
            float f7 = lrelu(vb.w*s_nsc[cb+7] + s_nsh[cb+7]);
            __half2 h0 = __floats2half2_rn(f0, f1);
            __half2 h1 = __floats2half2_rn(f2, f3);
            __half2 h2 = __floats2half2_rn(f4, f5);
            __half2 h3 = __floats2half2_rn(f6, f7);
            uint4 v; v.x = *(uint32_t*)&h0; v.y = *(uint32_t*)&h1;
            v.z = *(uint32_t*)&h2; v.w = *(uint32_t*)&h3;
            *(uint4*)(ab + px*272 + (8+kg)*16) = v;
        }
    }
    __syncthreads();

    float acc[2][4][4];
    #pragma unroll
    for (int mt = 0; mt < 2; mt++)
        #pragma unroll
        for (int nt = 0; nt < 4; nt++)
            #pragma unroll
            for (int r = 0; r < 4; r++) acc[mt][nt][r] = 0.f;

    uint32_t aBase = smem_u32(sA) + (uint32_t)(((wm*32 + (lane & 15))*A5_STRIDE_H
                    + ((lane >> 4) << 3)) * 2);
    uint32_t bBase = smem_u32(sW) + (uint32_t)(((wn*32 + (lane & 7) + ((lane >> 4) << 3))*W5_STRIDE_H
                    + (lane & 8)) * 2);

    #pragma unroll
    for (int ks = 0; ks < 8; ks++) {
        uint32_t a[2][4], bf[4][2];
        ldsm_x4(a[0][0], a[0][1], a[0][2], a[0][3], aBase + ks*32);
        ldsm_x4(a[1][0], a[1][1], a[1][2], a[1][3], aBase + 16*A5_STRIDE_H*2 + ks*32);
        ldsm_x4(bf[0][0], bf[0][1], bf[1][0], bf[1][1], bBase + ks*32);
        ldsm_x4(bf[2][0], bf[2][1], bf[3][0], bf[3][1], bBase + 16*W5_STRIDE_H*2 + ks*32);
        #pragma unroll
        for (int mt = 0; mt < 2; mt++)
            #pragma unroll
            for (int nt = 0; nt < 4; nt++)
                mma_f16_16n8k16(acc[mt][nt], a[mt], bf[nt]);
    }
    __syncthreads();

    conv_epilogue(acc, nullptr, &es, wm, wn, wid, lane, rA, qA, y, x0, cta, out);
}

// ---------------- launch ----------------
extern "C" void kernel_launch(void* const* d_in, const int* in_sizes, int n_in,
                              void* d_out, int out_size) {
    const float* x1d  = (const float*)d_in[0];
    const float* x2   = (const float*)d_in[1];
    const float* W1   = (const float*)d_in[2];
    const float* g1   = (const float*)d_in[3];
    const float* b1   = (const float*)d_in[4];
    const float* W2   = (const float*)d_in[5];
    const float* g2   = (const float*)d_in[6];
    const float* b2   = (const float*)d_in[7];
    const float* W3   = (const float*)d_in[8];
    const float* g3   = (const float*)d_in[9];
    const float* b3   = (const float*)d_in[10];
    const float* rw   = (const float*)d_in[11];
    const float* rb   = (const float*)d_in[12];
    const float* rg   = (const float*)d_in[13];
    const float* rbe  = (const float*)d_in[14];
    float* out = (float*)d_out;

    float *bP, *bR, *bX, *bT;
    __half* wh;
    cudaGetSymbolAddress((void**)&bP, g_bufP);
    cudaGetSymbolAddress((void**)&bR, g_bufR);
    cudaGetSymbolAddress((void**)&bX, g_bufX);
    cudaGetSymbolAddress((void**)&bT, g_bufT);
    cudaGetSymbolAddress((void**)&wh, g_wswh);

    cudaFuncSetAttribute(conv_mma<false>, cudaFuncAttributeMaxDynamicSharedMemorySize, CONV_SMEM);
    cudaFuncSetAttribute(conv_mma<true>,  cudaFuncAttributeMaxDynamicSharedMemorySize, CONV_SMEM);
    cudaFuncSetAttribute(k4_mma, cudaFuncAttributeMaxDynamicSharedMemorySize, CONV_SMEM);
    cudaFuncSetAttribute(k5_mma, cudaFuncAttributeMaxDynamicSharedMemorySize, MIX_SMEM);

    dim3 cgrid(3, 384);

    k_zero<<<1, 256>>>();                                   // #1
    k2_x2stats<<<dim3(36, 210), 256>>>(x2);                 // #2
    k2b_scaleW2<<<64, 256>>>(W2);                           // #3
    k4_mma<<<cgrid, 256, CONV_SMEM>>>(x2, bP);              // #4 (ncu window)
    k_finred<<<64, 256>>>(0, g2, b2);
    k_wprep<<<1440, 256>>>(rw);
    k_w3prep<<<32, 256>>>(W3);
    k1_norm1d<<<788, 384>>>(x1d);
    k3_rowcol<<<128, 384>>>(W1);
    k3b_pair1<<<64, 128>>>(g1, b1);
    k5_mma<<<cgrid, 256, MIX_SMEM>>>(bR);
    k_finred<<<64, 256>>>(1, g3, b3);
    k_apply_nhwc<<<9216, 256>>>((const float4*)bR, 1, nullptr, (float4*)bX);

    float* cur = bX;
    float* other = bP;
    const int DIL[5] = {1, 2, 4, 2, 1};
    for (int l = 0; l < 5; l++) {
        int D = DIL[l];
        int si0 = 2 + l*2, si1 = si0 + 1;
        // conv1: reads g_actH (fp16 NHWC copy of carrier), raw -> bR (NHWC)
        conv_mma<false><<<cgrid, 256, CONV_SMEM>>>(nullptr, 0, wh + (l*2)*36864, D,
                                                   rb + (l*2)*64, bR);
        k_finred<<<64, 256>>>(si0, rg + (l*2)*64, rbe + (l*2)*64);
        // conv2: reads bR fp32 NHWC raw with fused norm(si0), raw -> bT (NHWC)
        conv_mma<true><<<cgrid, 256, CONV_SMEM>>>(bR, si0, wh + (l*2+1)*36864, D,
                                                  rb + (l*2+1)*64, bT);
        k_finred<<<64, 256>>>(si1, rg + (l*2+1)*64, rbe + (l*2+1)*64);
        if (l < 4) {
            k_apply_nhwc<<<9216, 256>>>((const float4*)bT, si1, (const float4*)cur,
                                        (float4*)other);
            float* tmp = cur; cur = other; other = tmp;
        } else {
            k_apply_tr<<<2304, 256>>>(bT, si1, cur, out);
        }
    }
}